// round 8
// baseline (speedup 1.0000x reference)
#include <cuda_runtime.h>
#include <math.h>

// Batched FFT: B=8192 rows, N=4096, complex fp32 (separate re/im), out = [Yre; Yim].
//
// Radix-16^3 four-step, packed f32x2 arithmetic (round-7 WIN baseline, 82.7us).
// This round: twiddle stage critical path halved — w^8 reached by 3 scalar
// squarings, then TWO independent split-form recurrences (k=1..7 and k=8..15)
// advance in parallel (serial depth 15 -> 7, 2x ILP in the chain window).
//
//   n = n1*256 + n2, k = k2*16 + k1, n2 = p1*16 + p2, k2 = q2*16 + q1.
// Pass 1 (t=n2):   A[k1] = DFT16_{n1}(x[n1*256+t]) * W4096^{t*k1}
// Exch 1 (pad 257)
// Pass 2 (k1,p2):  C[q1] = DFT16_{p1}(...) * W256^{p2*q1}
// Exch 2
// Pass 3 (k1,q1):  Y[q2*256 + t] = DFT16_{p2}(...)

#define NFFT 4096
#define TPB  256

typedef unsigned long long c64;   // packed complex: lo 32 = re, hi 32 = im

__device__ __forceinline__ c64 cpack(float re, float im) {
    c64 r;
    asm("mov.b64 %0, {%1, %2};" : "=l"(r) : "f"(re), "f"(im));
    return r;
}
__device__ __forceinline__ void cunpack(c64 v, float& re, float& im) {
    asm("mov.b64 {%0, %1}, %2;" : "=f"(re), "=f"(im) : "l"(v));
}
__device__ __forceinline__ c64 padd(c64 a, c64 b) {
    c64 r;
    asm("add.rn.f32x2 %0, %1, %2;" : "=l"(r) : "l"(a), "l"(b));
    return r;
}
__device__ __forceinline__ c64 pmul(c64 a, c64 b) {
    c64 r;
    asm("mul.rn.f32x2 %0, %1, %2;" : "=l"(r) : "l"(a), "l"(b));
    return r;
}
__device__ __forceinline__ c64 pfma(c64 a, c64 b, c64 c) {
    c64 r;
    asm("fma.rn.f32x2 %0, %1, %2, %3;" : "=l"(r) : "l"(a), "l"(b), "l"(c));
    return r;
}
__device__ __forceinline__ c64 pswap(c64 a) {   // (re,im) -> (im,re)
    c64 r;
    asm("{\n\t.reg .b32 lo, hi;\n\tmov.b64 {lo, hi}, %1;\n\tmov.b64 %0, {hi, lo};\n\t}"
        : "=l"(r) : "l"(a));
    return r;
}

#define K_NEG1 cpack(-1.0f, -1.0f)
#define K_PM   cpack( 1.0f, -1.0f)
#define K_MP   cpack(-1.0f,  1.0f)

// a - b
__device__ __forceinline__ c64 psub(c64 a, c64 b) { return pfma(b, K_NEG1, a); }
// complex mul by twiddle held split: xx=(bx,bx), nyy=(-by,by)
__device__ __forceinline__ c64 cmul_t(c64 a, c64 xx, c64 nyy) {
    return pfma(a, xx, pmul(pswap(a), nyy));
}
// multiply by -i: (x,y) -> (y,-x)
__device__ __forceinline__ c64 cnegi(c64 a) { return pmul(pswap(a), K_PM); }

// forward DFT4 (W4 = -i), packed: 9 f32x2 ops
__device__ __forceinline__ void dft4(c64 a, c64 b, c64 c, c64 d,
                                     c64& o0, c64& o1, c64& o2, c64& o3) {
    c64 s0 = padd(a, c);
    c64 s1 = psub(a, c);
    c64 s2 = padd(b, d);
    c64 s3 = psub(b, d);
    o0 = padd(s0, s2);
    o2 = psub(s0, s2);
    c64 s3r = pswap(s3);
    o1 = pfma(s3r, K_PM, s1);   // s1 - i*s3
    o3 = pfma(s3r, K_MP, s1);   // s1 + i*s3
}

// 16-point forward DFT, natural in -> natural out (radix-4 x radix-4), packed.
__device__ __forceinline__ void fft16(c64 v[16]) {
    const float C1 = 0.92387953251128675613f;  // cos(pi/8)
    const float S1 = 0.38268343236508977173f;  // sin(pi/8)
    const float R  = 0.70710678118654752440f;  // sqrt(2)/2

    c64 a[4][4];
#pragma unroll
    for (int l = 0; l < 4; l++)
        dft4(v[l], v[l + 4], v[l + 8], v[l + 12],
             a[l][0], a[l][1], a[l][2], a[l][3]);

    // internal twiddles W16^{l*p} in split (xx, nyy) form
    a[1][1] = cmul_t(a[1][1], cpack( C1,  C1), cpack( S1, -S1));  // (C1,-S1)
    a[1][2] = cmul_t(a[1][2], cpack(  R,   R), cpack(  R,  -R));  // (R,-R)
    a[1][3] = cmul_t(a[1][3], cpack( S1,  S1), cpack( C1, -C1));  // (S1,-C1)
    a[2][1] = cmul_t(a[2][1], cpack(  R,   R), cpack(  R,  -R));  // (R,-R)
    a[2][2] = cnegi(a[2][2]);                                     // * -i
    a[2][3] = cmul_t(a[2][3], cpack( -R,  -R), cpack(  R,  -R));  // (-R,-R)
    a[3][1] = cmul_t(a[3][1], cpack( S1,  S1), cpack( C1, -C1));  // (S1,-C1)
    a[3][2] = cmul_t(a[3][2], cpack( -R,  -R), cpack(  R,  -R));  // (-R,-R)
    a[3][3] = cmul_t(a[3][3], cpack(-C1, -C1), cpack(-S1,  S1));  // (-C1,S1)

#pragma unroll
    for (int p = 0; p < 4; p++)
        dft4(a[0][p], a[1][p], a[2][p], a[3][p],
             v[p], v[4 + p], v[8 + p], v[12 + p]);
}

// v[k] *= w^k, k=1..15.  w^8 via 3 scalar squarings (depth 3); two independent
// split-form recurrences (A: k=1..7, B: k=8..15) advance in parallel.
__device__ __forceinline__ void twiddle16(c64 v[16], float ang) {
    float s, c;
    sincosf(ang, &s, &c);
    // scalar squarings to w^2, w^4, w^8
    float c2 = fmaf(c,  c,  -s  * s ),  s2 = 2.0f * c  * s;
    float c4 = fmaf(c2, c2, -s2 * s2),  s4 = 2.0f * c2 * s2;
    float c8 = fmaf(c4, c4, -s4 * s4),  s8 = 2.0f * c4 * s4;

    const c64 cwxx = cpack( c,  c);   // base w (advance step)
    const c64 wsnn = cpack(-s,  s);
    const c64 wsnp = cpack( s, -s);

    c64 caxx = cwxx;                  // A = w^1
    c64 sann = wsnn;
    c64 cbxx = cpack( c8, c8);        // B = w^8
    c64 sbnn = cpack(-s8, s8);

    v[8] = cmul_t(v[8], cbxx, sbnn);
#pragma unroll
    for (int k = 1; k < 8; k++) {
        v[k] = cmul_t(v[k], caxx, sann);
        // advance B to w^{8+k}, apply to v[8+k]
        c64 ncb = pfma(cbxx, cwxx, pmul(sbnn, wsnp));
        c64 nsb = pfma(sbnn, cwxx, pmul(cbxx, wsnn));
        cbxx = ncb; sbnn = nsb;
        v[8 + k] = cmul_t(v[8 + k], cbxx, sbnn);
        // advance A to w^{k+1}
        if (k < 7) {
            c64 nca = pfma(caxx, cwxx, pmul(sann, wsnp));
            c64 nsa = pfma(sann, cwxx, pmul(caxx, wsnn));
            caxx = nca; sann = nsa;
        }
    }
}

__global__ void __launch_bounds__(TPB, 4)
fft4096_kernel(const float* __restrict__ xre,
               const float* __restrict__ xim,
               float* __restrict__ out,
               int batch) {
    __shared__ c64 sh[16 * 257];  // 32896 B (257-stride pad for exch 1)

    const int b = blockIdx.x;
    const int t = threadIdx.x;

    const float* xr = xre + (size_t)b * NFFT;
    const float* xi = xim + (size_t)b * NFFT;

    c64 v[16];
#pragma unroll
    for (int n1 = 0; n1 < 16; n1++)
        v[n1] = cpack(__ldcs(&xr[n1 * 256 + t]), __ldcs(&xi[n1 * 256 + t]));

    // ---- pass 1: DFT16 over n1 (thread t = n2), twiddle W4096^{t*k1} ----
    fft16(v);
    twiddle16(v, (float)t * (-6.2831853071795864769f / 4096.0f));

    // ---- exchange 1: sh[k1*257 + n2] ----
#pragma unroll
    for (int k1 = 0; k1 < 16; k1++)
        sh[k1 * 257 + t] = v[k1];
    __syncthreads();

    {
        const int k1 = t & 15;
        const int p2 = t >> 4;
#pragma unroll
        for (int p1 = 0; p1 < 16; p1++)
            v[p1] = sh[k1 * 257 + p1 * 16 + p2];

        // ---- pass 2: DFT16 over p1 -> q1, twiddle W256^{p2*q1} ----
        fft16(v);
        twiddle16(v, (float)p2 * (-6.2831853071795864769f / 256.0f));
    }
    __syncthreads();

    // ---- exchange 2: sh[q1*256 + t] ----
#pragma unroll
    for (int q1 = 0; q1 < 16; q1++)
        sh[q1 * 256 + t] = v[q1];
    __syncthreads();

    {
        const int k1 = t & 15;
        const int q1 = t >> 4;
#pragma unroll
        for (int p2 = 0; p2 < 16; p2++)
            v[p2] = sh[q1 * 256 + p2 * 16 + k1];
    }

    // ---- pass 3: DFT16 over p2 -> q2;  Y[q2*256 + t] ----
    fft16(v);

    float* outre = out + (size_t)b * NFFT;
    float* outim = out + (size_t)batch * NFFT + (size_t)b * NFFT;
#pragma unroll
    for (int q2 = 0; q2 < 16; q2++) {
        float re, im;
        cunpack(v[q2], re, im);
        __stcs(&outre[q2 * 256 + t], re);
        __stcs(&outim[q2 * 256 + t], im);
    }
}

extern "C" void kernel_launch(void* const* d_in, const int* in_sizes, int n_in,
                              void* d_out, int out_size) {
    const float* xre = (const float*)d_in[0];
    const float* xim = (const float*)d_in[1];
    float* out = (float*)d_out;
    const int batch = in_sizes[0] / NFFT;

    fft4096_kernel<<<batch, TPB>>>(xre, xim, out, batch);
}